// round 5
// baseline (speedup 1.0000x reference)
#include <cuda_runtime.h>
#include <cstdint>

// Problem shape (fixed by reference setup_inputs)
#define NC    19
#define HWX   (512 * 1024)     // 524288 = 2^19
#define NPIX  (4 * HWX)        // 2097152 = 2^21
#define MIN_KEPT_K 100000

#define CHUNK        1024                      // pixels per loss block
#define LOSS_BLOCKS  (NPIX / CHUNK)            // 2048
#define CHUNKS_PER_N (HWX / CHUNK)             // 512
#define PLANE_BYTES  (CHUNK * 4)               // 4096
#define SMEM_DATA    1024                      // data region offset (mbar below)
#define SMEM_TOTAL   (SMEM_DATA + (NC + 1) * PLANE_BYTES)   // 82944
#define TX_BYTES     ((NC + 1) * PLANE_BYTES)  // 81920

#define P2_BLOCKS    256                       // pass2: 32 elems/thread
#define NBINS16      65536

// ---------------- device scratch (no allocations allowed) ----------------
__device__ float        g_loss[NPIX];          // 8 MB loss scratch
__device__ float        g_cand[NPIX];          // candidate compaction (worst case)
__device__ unsigned int g_hist16[NBINS16];     // 256 KB histogram, top 16 bits
__device__ unsigned int g_nvalid;
__device__ unsigned int g_prefix16;            // selected top-16-bit bin
__device__ unsigned int g_k;                   // remaining rank within bin
__device__ unsigned int g_ncand;
__device__ double       g_total_sum;           // fallback mean numerator
__device__ double       g_above_sum;
__device__ unsigned int g_above_cnt;
__device__ unsigned int g_done[2];

// ---------------- helpers ----------------
__device__ __forceinline__ uint32_t smem_u32(const void* p) {
    uint32_t a;
    asm("{ .reg .u64 t; cvta.to.shared.u64 t, %1; cvt.u32.u64 %0, t; }"
        : "=r"(a) : "l"(p));
    return a;
}

__device__ __forceinline__ void mbar_init(uint32_t mbar, uint32_t cnt) {
    asm volatile("mbarrier.init.shared.b64 [%0], %1;" :: "r"(mbar), "r"(cnt) : "memory");
}
__device__ __forceinline__ void mbar_expect_tx(uint32_t mbar, uint32_t bytes) {
    asm volatile("mbarrier.arrive.expect_tx.shared.b64 _, [%0], %1;"
                 :: "r"(mbar), "r"(bytes) : "memory");
}
__device__ __forceinline__ void mbar_wait0(uint32_t mbar) {
    asm volatile(
        "{\n\t.reg .pred P;\n\t"
        "W%=:\n\t"
        "mbarrier.try_wait.parity.acquire.cta.shared::cta.b64 P, [%0], 0, 0x989680;\n\t"
        "@!P bra W%=;\n\t}"
        :: "r"(mbar) : "memory");
}
__device__ __forceinline__ void bulk_g2s(uint32_t dst, const void* src, uint32_t bytes,
                                         uint32_t mbar) {
    asm volatile(
        "cp.async.bulk.shared::cta.global.mbarrier::complete_tx::bytes [%0], [%1], %2, [%3];"
        :: "r"(dst), "l"(src), "r"(bytes), "r"(mbar) : "memory");
}

// 256-thread inclusive suffix scan in shared memory (ss modified in place).
__device__ __forceinline__ void suffix_scan256(unsigned int* ss) {
    const int t = threadIdx.x;
    #pragma unroll
    for (int off = 1; off < 256; off <<= 1) {
        unsigned int v = (t + off < 256) ? ss[t + off] : 0u;
        __syncthreads();
        ss[t] += v;
        __syncthreads();
    }
}

// ---------------- init ----------------
__global__ void init_kernel() {
    const int i = blockIdx.x * 256 + threadIdx.x;     // grid 256 -> 65536 threads
    g_hist16[i] = 0u;
    if (i == 0) {
        g_nvalid = 0u; g_prefix16 = 0u; g_k = 0u; g_ncand = 0u;
        g_total_sum = 0.0; g_above_sum = 0.0; g_above_cnt = 0u;
        g_done[0] = 0u; g_done[1] = 0u;
    }
}

// Top-16-bit select over g_hist16 (runs in last loss block, 256 threads).
__device__ void select16_tail() {
    __shared__ unsigned int ss[256];
    __shared__ int owner;
    __shared__ unsigned int kbase;
    const int t = threadIdx.x;

    const unsigned int nv = *((volatile unsigned int*)&g_nvalid);
    if (nv == 0u) { if (t == 0) { g_prefix16 = 0u; g_k = 0u; } return; }

    int nk = (int)(0.7f * (float)nv);          // f32 mul + trunc, matches jax
    if (nk < MIN_KEPT_K) nk = MIN_KEPT_K;
    if ((unsigned int)nk > nv) nk = (int)nv;
    if (nk < 1) nk = 1;
    const unsigned int k = (unsigned int)nk;

    // phase 1: per-thread chunk totals (bins [t*256, t*256+256))
    const uint4* H = reinterpret_cast<const uint4*>(g_hist16);
    unsigned int sum = 0;
    #pragma unroll 8
    for (int j = 0; j < 64; j++) {
        const uint4 u = H[t * 64 + j];
        sum += u.x + u.y + u.z + u.w;
    }
    ss[t] = sum;
    __syncthreads();
    suffix_scan256(ss);
    const unsigned int above_chunk = (t + 1 < 256) ? ss[t + 1] : 0u;
    const unsigned int incl_chunk  = ss[t];
    __syncthreads();
    if (above_chunk < k && incl_chunk >= k) { owner = t; kbase = above_chunk; }
    __syncthreads();

    // phase 2: exact bin within owner's 256 bins
    const unsigned int h2 = g_hist16[owner * 256 + t];
    ss[t] = h2;
    __syncthreads();
    suffix_scan256(ss);
    const unsigned int above = kbase + ((t + 1 < 256) ? ss[t + 1] : 0u);
    if (above < k && above + h2 >= k) {
        g_prefix16 = (unsigned int)(owner * 256 + t);
        g_k = k - above;
    }
}

// Fused: TMA-tiled NLL, loss write, validity count, fallback sum, 16-bit
// gmem histogram; last block selects the top-16-bit prefix.
__global__ void __launch_bounds__(256) loss_kernel(
    const float* __restrict__ logits,
    const int* __restrict__ targets)
{
    extern __shared__ char smem[];
    __shared__ unsigned int sval;
    __shared__ float wsum[8];
    __shared__ bool  lastf;

    const uint32_t sb   = smem_u32(smem);
    const uint32_t mbar = sb;                       // 16B-aligned
    const int t = threadIdx.x;
    const int b = blockIdx.x;

    if (t == 0) { sval = 0u; mbar_init(mbar, 1); }
    __syncthreads();

    if (t == 0) {
        const int n   = b / CHUNKS_PER_N;
        const int hw0 = (b % CHUNKS_PER_N) * CHUNK;
        mbar_expect_tx(mbar, TX_BYTES);
        const float* pl = logits + ((size_t)n * NC) * HWX + hw0;
        #pragma unroll
        for (int c = 0; c < NC; c++)
            bulk_g2s(sb + SMEM_DATA + c * PLANE_BYTES, pl + (size_t)c * HWX,
                     PLANE_BYTES, mbar);
        bulk_g2s(sb + SMEM_DATA + NC * PLANE_BYTES, targets + (size_t)b * CHUNK,
                 PLANE_BYTES, mbar);
    }
    mbar_wait0(mbar);

    // compute: 4 pixels per thread from smem
    const char* data = smem + SMEM_DATA;
    const int4 tg = *reinterpret_cast<const int4*>(data + NC * PLANE_BYTES + t * 16);

    float4 s  = make_float4(0.f, 0.f, 0.f, 0.f);
    float4 xt = make_float4(0.f, 0.f, 0.f, 0.f);    // tg in [0,NC) -> set once
    #pragma unroll
    for (int c = 0; c < NC; c++) {
        const float4 v = *reinterpret_cast<const float4*>(data + c * PLANE_BYTES + t * 16);
        s.x += __expf(v.x);  s.y += __expf(v.y);
        s.z += __expf(v.z);  s.w += __expf(v.w);
        xt.x = (tg.x == c) ? v.x : xt.x;
        xt.y = (tg.y == c) ? v.y : xt.y;
        xt.z = (tg.z == c) ? v.z : xt.z;
        xt.w = (tg.w == c) ? v.w : xt.w;
    }

    const float l0 = __logf(s.x) - xt.x;
    const float l1 = __logf(s.y) - xt.y;
    const float l2 = __logf(s.z) - xt.z;
    const float l3 = __logf(s.w) - xt.w;

    *reinterpret_cast<float4*>(&g_loss[b * CHUNK + 4 * t]) = make_float4(l0, l1, l2, l3);

    unsigned int cnt = 0;
    if (l0 > 0.0f) { atomicAdd(&g_hist16[__float_as_uint(l0) >> 16], 1u); cnt++; }
    if (l1 > 0.0f) { atomicAdd(&g_hist16[__float_as_uint(l1) >> 16], 1u); cnt++; }
    if (l2 > 0.0f) { atomicAdd(&g_hist16[__float_as_uint(l2) >> 16], 1u); cnt++; }
    if (l3 > 0.0f) { atomicAdd(&g_hist16[__float_as_uint(l3) >> 16], 1u); cnt++; }
    if (cnt) atomicAdd(&sval, cnt);

    // block-reduce total sum (n_valid == 0 fallback path)
    float ls = l0 + l1 + l2 + l3;
    #pragma unroll
    for (int o = 16; o; o >>= 1) ls += __shfl_down_sync(0xffffffffu, ls, o);
    if ((t & 31) == 0) wsum[t >> 5] = ls;
    __syncthreads();
    if (t < 8) {
        float x = wsum[t];
        #pragma unroll
        for (int o = 4; o; o >>= 1) x += __shfl_down_sync(0xffu, x, o);
        if (t == 0) atomicAdd(&g_total_sum, (double)x);
    }
    if (t == 0 && sval) atomicAdd(&g_nvalid, sval);

    // last-block tail: top-16-bit select
    __threadfence();
    __syncthreads();
    if (t == 0) lastf = (atomicAdd(&g_done[0], 1u) == (unsigned)(LOSS_BLOCKS - 1));
    __syncthreads();
    if (lastf) { __threadfence(); select16_tail(); }
}

// Pass 2: single read of g_loss. Accumulate sum/cnt of elements in bins
// strictly above the prefix; compact prefix-matching candidates. Last block
// finishes the low-16-bit select and writes the result.
__global__ void __launch_bounds__(256) pass2_kernel(float* __restrict__ out) {
    __shared__ float  wsumf[8];
    __shared__ int    wcnt[8];
    __shared__ bool   lastf;
    __shared__ unsigned int hist[256];
    __shared__ unsigned int ss[256];

    const int t = threadIdx.x;
    const unsigned int pref = g_prefix16;
    const int base4 = blockIdx.x * (256 * 8);        // in float4 units

    float4 v[8];
    #pragma unroll
    for (int j = 0; j < 8; j++)
        v[j] = reinterpret_cast<const float4*>(g_loss)[base4 + j * 256 + t];

    float s = 0.0f;
    int   c = 0;
    #pragma unroll
    for (int j = 0; j < 8; j++) {
        const float a[4] = {v[j].x, v[j].y, v[j].z, v[j].w};
        #pragma unroll
        for (int e = 0; e < 4; e++) {
            const float    av = a[e];
            const unsigned bb = __float_as_uint(av);
            const bool pos  = (av > 0.0f);
            const bool abov = pos && ((bb >> 16) > pref);
            const bool cand = pos && ((bb >> 16) == pref);
            if (abov) { s += av; c++; }
            // warp-aggregated compaction of candidates
            const unsigned m = __ballot_sync(0xffffffffu, cand);
            if (m) {
                const int lane   = t & 31;
                const int leader = __ffs(m) - 1;
                unsigned base = 0;
                if (lane == leader) base = atomicAdd(&g_ncand, (unsigned)__popc(m));
                base = __shfl_sync(0xffffffffu, base, leader);
                if (cand) g_cand[base + __popc(m & ((1u << lane) - 1u))] = av;
            }
        }
    }

    #pragma unroll
    for (int o = 16; o; o >>= 1) {
        s += __shfl_down_sync(0xffffffffu, s, o);
        c += __shfl_down_sync(0xffffffffu, c, o);
    }
    if ((t & 31) == 0) { wsumf[t >> 5] = s; wcnt[t >> 5] = c; }
    __syncthreads();
    if (t < 8) {
        float x  = wsumf[t];
        int   cc = wcnt[t];
        #pragma unroll
        for (int o = 4; o; o >>= 1) {
            x  += __shfl_down_sync(0xffu, x, o);
            cc += __shfl_down_sync(0xffu, cc, o);
        }
        if (t == 0) {
            if (x != 0.0f) atomicAdd(&g_above_sum, (double)x);
            if (cc)        atomicAdd(&g_above_cnt, (unsigned)cc);
        }
    }

    __threadfence();
    __syncthreads();
    if (t == 0) lastf = (atomicAdd(&g_done[1], 1u) == (unsigned)(P2_BLOCKS - 1));
    __syncthreads();
    if (!lastf) return;
    __threadfence();

    // ---- final tail: low-16-bit select over candidates ----
    const unsigned int nv = *((volatile unsigned int*)&g_nvalid);
    if (nv == 0u) {
        if (t == 0) out[0] = (float)(*((volatile double*)&g_total_sum) / (double)NPIX);
        return;
    }

    const unsigned int n  = *((volatile unsigned int*)&g_ncand);
    unsigned int k = g_k;                 // rank within the prefix bin (>=1)
    unsigned int d1 = 0, d0 = 0;

    // round 1: bits [15:8]
    hist[t] = 0u; __syncthreads();
    for (unsigned int i = t; i < n; i += 256) {
        const unsigned int bb = __float_as_uint(((volatile float*)g_cand)[i]);
        atomicAdd(&hist[(bb >> 8) & 255u], 1u);
    }
    __syncthreads();
    {
        const unsigned int h = hist[t];
        ss[t] = h; __syncthreads();
        suffix_scan256(ss);
        const unsigned int above = (t + 1 < 256) ? ss[t + 1] : 0u;
        __syncthreads();
        if (above < k && above + h >= k) { hist[0] = (unsigned)t | ((k - above) << 16); }
        __syncthreads();
        d1 = hist[0] & 0xFFu;
        k  = hist[0] >> 16;
        __syncthreads();
    }

    // round 2: bits [7:0] among digit-d1 matches
    hist[t] = 0u; __syncthreads();
    for (unsigned int i = t; i < n; i += 256) {
        const unsigned int bb = __float_as_uint(((volatile float*)g_cand)[i]);
        if (((bb >> 8) & 255u) == d1) atomicAdd(&hist[bb & 255u], 1u);
    }
    __syncthreads();
    {
        const unsigned int h = hist[t];
        ss[t] = h; __syncthreads();
        suffix_scan256(ss);
        const unsigned int above = (t + 1 < 256) ? ss[t + 1] : 0u;
        __syncthreads();
        if (above < k && above + h >= k) { hist[0] = (unsigned)t; }
        __syncthreads();
        d0 = hist[0];
        __syncthreads();
    }

    const unsigned int thresh = (pref << 16) | (d1 << 8) | d0;

    // sum/count candidates >= threshold (uint order == float order, all > 0)
    float cs = 0.0f; int cc = 0;
    for (unsigned int i = t; i < n; i += 256) {
        const float av = ((volatile float*)g_cand)[i];
        if (__float_as_uint(av) >= thresh) { cs += av; cc++; }
    }
    #pragma unroll
    for (int o = 16; o; o >>= 1) {
        cs += __shfl_down_sync(0xffffffffu, cs, o);
        cc += __shfl_down_sync(0xffffffffu, cc, o);
    }
    if ((t & 31) == 0) { wsumf[t >> 5] = cs; wcnt[t >> 5] = cc; }
    __syncthreads();
    if (t < 8) {
        float x = wsumf[t]; int y = wcnt[t];
        #pragma unroll
        for (int o = 4; o; o >>= 1) {
            x += __shfl_down_sync(0xffu, x, o);
            y += __shfl_down_sync(0xffu, y, o);
        }
        if (t == 0) {
            const double ks = *((volatile double*)&g_above_sum) + (double)x;
            unsigned int kc = *((volatile unsigned int*)&g_above_cnt) + (unsigned)y;
            if (kc == 0u) kc = 1u;
            out[0] = (float)(ks / (double)kc);
        }
    }
}

// ---------------- entry point ----------------
extern "C" void kernel_launch(void* const* d_in, const int* in_sizes, int n_in,
                              void* d_out, int out_size) {
    const float* logits  = (const float*)d_in[0];
    const int*   targets = (const int*)d_in[1];
    float*       out     = (float*)d_out;

    static int smem_set = 0;
    if (!smem_set) {
        cudaFuncSetAttribute(loss_kernel,
                             cudaFuncAttributeMaxDynamicSharedMemorySize, SMEM_TOTAL);
        smem_set = 1;
    }

    init_kernel<<<256, 256>>>();
    loss_kernel<<<LOSS_BLOCKS, 256, SMEM_TOTAL>>>(logits, targets);
    pass2_kernel<<<P2_BLOCKS, 256>>>(out);
}

// round 6
// speedup vs baseline: 7.6181x; 7.6181x over previous
#include <cuda_runtime.h>

// Problem shape (fixed by reference setup_inputs)
#define NC   19
#define HWX  (512 * 1024)     // 524288 = 2^19
#define NPIX (4 * HWX)        // 2097152 = 2^21
#define MIN_KEPT_K 100000

#define LOSS_BLOCKS (NPIX / (256 * 4))    // 2048  (4 pixels / thread)
#define SCAN_BLOCKS (NPIX / (256 * 8))    // 1024  (8 elems / thread, 2x float4)

// ---------------- device scratch (no allocations allowed) ----------------
__device__ float        g_loss[NPIX];       // 8 MB loss scratch
__device__ unsigned int g_hist[256];
__device__ unsigned int g_nvalid;
__device__ unsigned int g_prefix;           // radix-select accumulated bits
__device__ unsigned int g_k;                // remaining rank
__device__ double       g_total_sum;        // fallback mean numerator
__device__ double       g_kept_sum;
__device__ unsigned int g_kept_cnt;
__device__ unsigned int g_done[5];          // per-pass last-block counters

// ---------------- init ----------------
__global__ void init_kernel() {
    int t = threadIdx.x;
    g_hist[t] = 0u;
    if (t < 5) g_done[t] = 0u;
    if (t == 0) {
        g_nvalid    = 0u;
        g_prefix    = 0u;
        g_k         = 0u;
        g_total_sum = 0.0;
        g_kept_sum  = 0.0;
        g_kept_cnt  = 0u;
    }
}

// One radix-digit selection over the 256-bin histogram. Runs inside the
// tail of the producing kernel (all 256 threads of the last block).
__device__ void do_select(int first) {
    __shared__ unsigned int h[256];
    __shared__ unsigned int ss[256];
    const int t = threadIdx.x;
    const unsigned int hv = *((volatile unsigned int*)&g_hist[t]);
    h[t]  = hv;
    ss[t] = hv;
    __syncthreads();
    // inclusive suffix sum: ss[t] = sum_{j>=t} h[j]
    #pragma unroll
    for (int off = 1; off < 256; off <<= 1) {
        unsigned int v = (t + off < 256) ? ss[t + off] : 0u;
        __syncthreads();
        ss[t] += v;
        __syncthreads();
    }
    unsigned int k;
    if (first) {
        const unsigned int nv = *((volatile unsigned int*)&g_nvalid);
        int nk = (int)(0.7f * (float)nv);     // f32 mul + trunc, matches jax
        if (nk < MIN_KEPT_K) nk = MIN_KEPT_K;
        if ((unsigned int)nk > nv) nk = (int)nv;
        if (nk < 1) nk = 1;
        k = (unsigned int)nk;
    } else {
        k = g_k;
    }
    const unsigned int incl  = ss[t];
    const unsigned int above = incl - h[t];
    if (above < k && incl >= k) {             // unique thread (h[t] > 0)
        g_prefix = (g_prefix << 8) | (unsigned int)t;
        g_k = k - above;
    }
    g_hist[t] = 0u;                           // ready for next pass
}

// Fused: per-pixel NLL, loss scratch write, validity count, fallback sum,
// top-8-bit histogram, and (in the last block) the first radix select.
__global__ void __launch_bounds__(256) loss_kernel(
    const float* __restrict__ logits,
    const int* __restrict__ targets)          // int32 (jax x64 disabled)
{
    __shared__ unsigned int sh[256];
    __shared__ unsigned int sval;
    __shared__ float wsum[8];
    __shared__ bool  lastf;

    const int t = threadIdx.x;
    sh[t] = 0u;
    if (t == 0) sval = 0u;
    __syncthreads();

    const int p  = (blockIdx.x * 256 + t) * 4;     // first of 4 pixels
    const int n  = p >> 19;
    const int hw = p & (HWX - 1);
    const float* base = logits + ((size_t)n * NC) * HWX + hw;

    const int4 tg = *reinterpret_cast<const int4*>(targets + p);

    float4 s  = make_float4(0.f, 0.f, 0.f, 0.f);
    float4 xt = make_float4(0.f, 0.f, 0.f, 0.f);   // tg in [0,NC) -> set once
    #pragma unroll
    for (int c = 0; c < NC; c++) {
        const float4 v = __ldg(reinterpret_cast<const float4*>(base + (size_t)c * HWX));
        s.x += __expf(v.x);  s.y += __expf(v.y);
        s.z += __expf(v.z);  s.w += __expf(v.w);
        xt.x = (tg.x == c) ? v.x : xt.x;
        xt.y = (tg.y == c) ? v.y : xt.y;
        xt.z = (tg.z == c) ? v.z : xt.z;
        xt.w = (tg.w == c) ? v.w : xt.w;
    }

    float l0 = __logf(s.x) - xt.x;
    float l1 = __logf(s.y) - xt.y;
    float l2 = __logf(s.z) - xt.z;
    float l3 = __logf(s.w) - xt.w;

    *reinterpret_cast<float4*>(&g_loss[p]) = make_float4(l0, l1, l2, l3);

    unsigned int cnt = 0;
    if (l0 > 0.0f) { atomicAdd(&sh[__float_as_uint(l0) >> 24], 1u); cnt++; }
    if (l1 > 0.0f) { atomicAdd(&sh[__float_as_uint(l1) >> 24], 1u); cnt++; }
    if (l2 > 0.0f) { atomicAdd(&sh[__float_as_uint(l2) >> 24], 1u); cnt++; }
    if (l3 > 0.0f) { atomicAdd(&sh[__float_as_uint(l3) >> 24], 1u); cnt++; }
    if (cnt) atomicAdd(&sval, cnt);

    // block-reduce total sum (n_valid == 0 fallback path)
    float ls = l0 + l1 + l2 + l3;
    #pragma unroll
    for (int o = 16; o; o >>= 1) ls += __shfl_down_sync(0xffffffffu, ls, o);
    if ((t & 31) == 0) wsum[t >> 5] = ls;
    __syncthreads();
    if (t < 8) {
        float x = wsum[t];
        #pragma unroll
        for (int o = 4; o; o >>= 1) x += __shfl_down_sync(0xffu, x, o);
        if (t == 0) atomicAdd(&g_total_sum, (double)x);
    }

    if (sh[t]) atomicAdd(&g_hist[t], sh[t]);
    if (t == 0 && sval) atomicAdd(&g_nvalid, sval);

    // last-block-done tail -> fused select
    __threadfence();
    __syncthreads();
    if (t == 0) lastf = (atomicAdd(&g_done[0], 1u) == (unsigned)(LOSS_BLOCKS - 1));
    __syncthreads();
    if (lastf) { __threadfence(); do_select(1); }
}

// Histogram the next 8-bit digit among elements matching the current prefix,
// then (last block) fused select. shift in {16, 8, 0}.
__global__ void __launch_bounds__(256) refine_kernel(int shift, int pass) {
    __shared__ unsigned int sh[256];
    __shared__ bool lastf;
    const int t = threadIdx.x;
    sh[t] = 0u;
    __syncthreads();

    const unsigned int pref = g_prefix;
    const int base4 = blockIdx.x * (256 * 2);       // in float4 units
    #pragma unroll
    for (int j = 0; j < 2; j++) {
        const float4 v = reinterpret_cast<const float4*>(g_loss)[base4 + j * 256 + t];
        const float a[4] = {v.x, v.y, v.z, v.w};
        #pragma unroll
        for (int e = 0; e < 4; e++) {
            if (a[e] > 0.0f) {
                const unsigned int b = __float_as_uint(a[e]);
                if ((b >> (shift + 8)) == pref)
                    atomicAdd(&sh[(b >> shift) & 255u], 1u);
            }
        }
    }
    __syncthreads();
    if (sh[t]) atomicAdd(&g_hist[t], sh[t]);

    __threadfence();
    __syncthreads();
    if (t == 0) lastf = (atomicAdd(&g_done[pass], 1u) == (unsigned)(SCAN_BLOCKS - 1));
    __syncthreads();
    if (lastf) { __threadfence(); do_select(0); }
}

// Sum + count of losses >= exact k-th-largest threshold; last block finalizes.
__global__ void __launch_bounds__(256) final_sum_kernel(float* __restrict__ out) {
    __shared__ float  wsum[8];
    __shared__ int    wcnt[8];
    __shared__ bool   lastf;

    const float thresh = __uint_as_float(g_prefix);
    const int t = threadIdx.x;
    const int base4 = blockIdx.x * (256 * 2);

    float s = 0.0f;
    int   c = 0;
    #pragma unroll
    for (int j = 0; j < 2; j++) {
        const float4 v = reinterpret_cast<const float4*>(g_loss)[base4 + j * 256 + t];
        if (v.x >= thresh) { s += v.x; c++; }
        if (v.y >= thresh) { s += v.y; c++; }
        if (v.z >= thresh) { s += v.z; c++; }
        if (v.w >= thresh) { s += v.w; c++; }
    }

    #pragma unroll
    for (int o = 16; o; o >>= 1) {
        s += __shfl_down_sync(0xffffffffu, s, o);
        c += __shfl_down_sync(0xffffffffu, c, o);
    }
    if ((t & 31) == 0) { wsum[t >> 5] = s; wcnt[t >> 5] = c; }
    __syncthreads();
    if (t < 8) {
        float x  = wsum[t];
        int   cc = wcnt[t];
        #pragma unroll
        for (int o = 4; o; o >>= 1) {
            x  += __shfl_down_sync(0xffu, x, o);
            cc += __shfl_down_sync(0xffu, cc, o);
        }
        if (t == 0) {
            atomicAdd(&g_kept_sum, (double)x);
            atomicAdd(&g_kept_cnt, (unsigned int)cc);
        }
    }

    __threadfence();
    __syncthreads();
    if (t == 0) lastf = (atomicAdd(&g_done[4], 1u) == (unsigned)(SCAN_BLOCKS - 1));
    __syncthreads();
    if (lastf && t == 0) {
        __threadfence();
        const unsigned int nv = *((volatile unsigned int*)&g_nvalid);
        if (nv > 0u) {
            unsigned int kc = *((volatile unsigned int*)&g_kept_cnt);
            if (kc == 0u) kc = 1u;
            const double ks = *((volatile double*)&g_kept_sum);
            out[0] = (float)(ks / (double)kc);
        } else {
            const double ts = *((volatile double*)&g_total_sum);
            out[0] = (float)(ts / (double)NPIX);
        }
    }
}

// ---------------- entry point ----------------
extern "C" void kernel_launch(void* const* d_in, const int* in_sizes, int n_in,
                              void* d_out, int out_size) {
    const float* logits  = (const float*)d_in[0];
    const int*   targets = (const int*)d_in[1];
    float*       out     = (float*)d_out;

    init_kernel<<<1, 256>>>();
    loss_kernel<<<LOSS_BLOCKS, 256>>>(logits, targets);
    refine_kernel<<<SCAN_BLOCKS, 256>>>(16, 1);
    refine_kernel<<<SCAN_BLOCKS, 256>>>(8, 2);
    refine_kernel<<<SCAN_BLOCKS, 256>>>(0, 3);
    final_sum_kernel<<<SCAN_BLOCKS, 256>>>(out);
}

// round 7
// speedup vs baseline: 9.6434x; 1.2659x over previous
#include <cuda_runtime.h>

// Problem shape (fixed by reference setup_inputs)
#define NC   19
#define HWX  (512 * 1024)     // 524288 = 2^19
#define NPIX (4 * HWX)        // 2097152 = 2^21
#define MIN_KEPT_K 100000

#define GRID  512
#define BLOCK 256
#define PPB   (NPIX / GRID)        // 4096 pixels per block
#define ITERS (PPB / (BLOCK * 4))  // 4 iterations of 4 pixels/thread
#define SCAN_I (PPB / BLOCK)       // 16 smem elements per thread per scan

// ---------------- device scratch (no allocations allowed) ----------------
__device__ unsigned int g_h[4][256];    // per-round merged histograms
__device__ unsigned int g_cnt[8];       // grid-barrier counters (self-resetting)
__device__ unsigned int g_nvalid;
__device__ double       g_total_sum;    // fallback mean numerator
__device__ double       g_kept_sum;
__device__ unsigned int g_kept_cnt;

// ---------------- init (tiny, per graph replay) ----------------
__global__ void init_kernel() {
    const int t = threadIdx.x;
    g_h[0][t] = 0u; g_h[1][t] = 0u; g_h[2][t] = 0u; g_h[3][t] = 0u;
    if (t < 8) g_cnt[t] = 0u;
    if (t == 0) {
        g_nvalid = 0u; g_total_sum = 0.0; g_kept_sum = 0.0; g_kept_cnt = 0u;
    }
}

// ---------------- grid barrier (all blocks resident by construction) -----
__device__ __forceinline__ void gbar(int i) {
    __syncthreads();
    if (threadIdx.x == 0) {
        __threadfence();
        atomicAdd(&g_cnt[i], 1u);
        while (*((volatile unsigned int*)&g_cnt[i]) < (unsigned)GRID) {}
        __threadfence();
    }
    __syncthreads();
}

// Redundant per-block radix-digit select over a 256-bin global histogram.
// All blocks compute the identical (digit, k_remaining). ss: 256-word scratch.
__device__ __forceinline__ void sel256(const unsigned int* gh, unsigned int k,
                                       unsigned int* ss,
                                       unsigned int* s_dig, unsigned int* s_k,
                                       unsigned int& dig, unsigned int& krem) {
    const int t = threadIdx.x;
    if (t == 0) { *s_dig = 0u; *s_k = 1u; }        // defaults (nv==0 robustness)
    const unsigned int h = *((volatile const unsigned int*)&gh[t]);
    ss[t] = h;
    __syncthreads();
    #pragma unroll
    for (int off = 1; off < 256; off <<= 1) {      // inclusive suffix sum
        unsigned int v = (t + off < 256) ? ss[t + off] : 0u;
        __syncthreads();
        ss[t] += v;
        __syncthreads();
    }
    const unsigned int incl  = ss[t];
    const unsigned int above = incl - h;
    if (above < k && incl >= k) { *s_dig = (unsigned)t; *s_k = k - above; }
    __syncthreads();
    dig  = *s_dig;
    krem = *s_k;
    __syncthreads();
}

// ---------------- the persistent kernel ----------------
__global__ void __launch_bounds__(BLOCK, 4) ohem_kernel(
    const float* __restrict__ logits,
    const int*   __restrict__ targets,     // int32 (jax x64 disabled)
    float*       __restrict__ out)
{
    __shared__ float        sl[PPB];       // this block's losses (16 KB)
    __shared__ unsigned int sh[256];
    __shared__ unsigned int ss[256];
    __shared__ unsigned int s_dig, s_k;
    __shared__ float        rs[8];
    __shared__ int          rc[8];

    const int t = threadIdx.x;
    const int b = blockIdx.x;

    sh[t] = 0u;
    __syncthreads();

    // ---- phase 1: compute losses into smem; local 8-bit hist + stats ----
    float lsum = 0.0f;
    int   lval = 0;
    #pragma unroll
    for (int j = 0; j < ITERS; j++) {
        const int p  = b * PPB + j * (BLOCK * 4) + t * 4;
        const int n  = p >> 19;
        const int hw = p & (HWX - 1);
        const float* base = logits + ((size_t)n * NC) * HWX + hw;
        const int4 tg = *reinterpret_cast<const int4*>(targets + p);

        float4 s  = make_float4(0.f, 0.f, 0.f, 0.f);
        float4 xt = make_float4(0.f, 0.f, 0.f, 0.f);   // tg in [0,NC) -> set once
        #pragma unroll
        for (int c = 0; c < NC; c++) {
            const float4 v = __ldg(reinterpret_cast<const float4*>(base + (size_t)c * HWX));
            s.x += __expf(v.x);  s.y += __expf(v.y);
            s.z += __expf(v.z);  s.w += __expf(v.w);
            xt.x = (tg.x == c) ? v.x : xt.x;
            xt.y = (tg.y == c) ? v.y : xt.y;
            xt.z = (tg.z == c) ? v.z : xt.z;
            xt.w = (tg.w == c) ? v.w : xt.w;
        }
        const float l0 = __logf(s.x) - xt.x;
        const float l1 = __logf(s.y) - xt.y;
        const float l2 = __logf(s.z) - xt.z;
        const float l3 = __logf(s.w) - xt.w;

        *reinterpret_cast<float4*>(&sl[j * (BLOCK * 4) + t * 4]) =
            make_float4(l0, l1, l2, l3);

        if (l0 > 0.0f) { atomicAdd(&sh[__float_as_uint(l0) >> 24], 1u); lval++; }
        if (l1 > 0.0f) { atomicAdd(&sh[__float_as_uint(l1) >> 24], 1u); lval++; }
        if (l2 > 0.0f) { atomicAdd(&sh[__float_as_uint(l2) >> 24], 1u); lval++; }
        if (l3 > 0.0f) { atomicAdd(&sh[__float_as_uint(l3) >> 24], 1u); lval++; }
        lsum += l0 + l1 + l2 + l3;
    }

    // block-reduce lsum / lval
    #pragma unroll
    for (int o = 16; o; o >>= 1) {
        lsum += __shfl_down_sync(0xffffffffu, lsum, o);
        lval += __shfl_down_sync(0xffffffffu, lval, o);
    }
    if ((t & 31) == 0) { rs[t >> 5] = lsum; rc[t >> 5] = lval; }
    __syncthreads();
    if (t < 8) {
        float x = rs[t]; int y = rc[t];
        #pragma unroll
        for (int o = 4; o; o >>= 1) {
            x += __shfl_down_sync(0xffu, x, o);
            y += __shfl_down_sync(0xffu, y, o);
        }
        if (t == 0) {
            if (y) atomicAdd(&g_nvalid, (unsigned)y);
            atomicAdd(&g_total_sum, (double)x);
        }
    }
    if (sh[t]) atomicAdd(&g_h[0][t], sh[t]);   // sparse merge (few nonzero bins)

    gbar(0);

    // ---- phase 2: 4-round radix select (redundant per block) ----
    const unsigned int nv = *((volatile unsigned int*)&g_nvalid);
    unsigned int k;
    {
        int nk = (int)(0.7f * (float)nv);      // f32 mul + trunc, matches jax
        if (nk < MIN_KEPT_K) nk = MIN_KEPT_K;
        if ((unsigned)nk > nv) nk = (int)nv;
        if (nk < 1) nk = 1;
        k = (unsigned)nk;
    }

    unsigned int dig, pref;
    sel256(g_h[0], k, ss, &s_dig, &s_k, dig, k);
    pref = dig;

    #pragma unroll
    for (int r = 1; r < 4; r++) {
        const int shm = 24 - 8 * r;            // 16, 8, 0
        sh[t] = 0u;
        __syncthreads();
        #pragma unroll
        for (int i = 0; i < SCAN_I; i++) {
            const float v = sl[i * BLOCK + t];
            if (v > 0.0f) {
                const unsigned int bb = __float_as_uint(v);
                if ((bb >> (shm + 8)) == pref)
                    atomicAdd(&sh[(bb >> shm) & 255u], 1u);
            }
        }
        __syncthreads();
        if (sh[t]) atomicAdd(&g_h[r][t], sh[t]);
        gbar(r);
        sel256(g_h[r], k, ss, &s_dig, &s_k, dig, k);
        pref = (pref << 8) | dig;
    }

    // ---- phase 3: masked sum/count over smem losses ----
    const float fth = __uint_as_float(pref);   // exact k-th-largest (> 0)
    float s = 0.0f;
    int   c = 0;
    #pragma unroll
    for (int i = 0; i < SCAN_I; i++) {
        const float v = sl[i * BLOCK + t];
        if (v >= fth) { s += v; c++; }
    }
    #pragma unroll
    for (int o = 16; o; o >>= 1) {
        s += __shfl_down_sync(0xffffffffu, s, o);
        c += __shfl_down_sync(0xffffffffu, c, o);
    }
    if ((t & 31) == 0) { rs[t >> 5] = s; rc[t >> 5] = c; }
    __syncthreads();
    if (t < 8) {
        float x = rs[t]; int y = rc[t];
        #pragma unroll
        for (int o = 4; o; o >>= 1) {
            x += __shfl_down_sync(0xffu, x, o);
            y += __shfl_down_sync(0xffu, y, o);
        }
        if (t == 0) {
            atomicAdd(&g_kept_sum, (double)x);
            if (y) atomicAdd(&g_kept_cnt, (unsigned)y);
        }
    }
    __syncthreads();

    // ---- final: arrive-only barrier; block 0 finalizes + resets ----
    if (t == 0) {
        __threadfence();
        atomicAdd(&g_cnt[4], 1u);
        if (b == 0) {
            while (*((volatile unsigned int*)&g_cnt[4]) < (unsigned)GRID) {}
            __threadfence();
            if (nv > 0u) {
                unsigned int kc = *((volatile unsigned int*)&g_kept_cnt);
                if (kc == 0u) kc = 1u;
                const double ks = *((volatile double*)&g_kept_sum);
                out[0] = (float)(ks / (double)kc);
            } else {
                out[0] = (float)(*((volatile double*)&g_total_sum) / (double)NPIX);
            }
            // self-reset barrier counters for the next graph replay
            #pragma unroll
            for (int i = 0; i < 8; i++) g_cnt[i] = 0u;
        }
    }
}

// ---------------- entry point ----------------
extern "C" void kernel_launch(void* const* d_in, const int* in_sizes, int n_in,
                              void* d_out, int out_size) {
    const float* logits  = (const float*)d_in[0];
    const int*   targets = (const int*)d_in[1];
    float*       out     = (float*)d_out;

    init_kernel<<<1, 256>>>();
    ohem_kernel<<<GRID, BLOCK>>>(logits, targets, out);
}